// round 10
// baseline (speedup 1.0000x reference)
#include <cuda_runtime.h>

// Scaled dot-product attention, B=4 H=16 S=2048 D=64, fp32 in/out.
// Round 9: R6 tf32-MMA layout + cp.async double-buffered K/V pipeline.
// Prepass converts Q/K/V to tf32 bits (Q pre-scaled to log2 domain) into
// __device__ scratch, so the main loop stages tiles with raw cp.async.

#define DH 64
#define BM 128
#define BN 128
#define NT 256

#define KS_STRIDE 68   /* words per K row: conflict-free B-fragment pattern */
#define VS_STRIDE 72   /* words per V row */
#define KS_BYTES (BN * KS_STRIDE * 4)       /* 34816 */
#define VS_BYTES (BN * VS_STRIDE * 4)       /* 36864 */
#define BUF_BYTES (KS_BYTES + VS_BYTES)     /* 71680 */
#define SMEM_BYTES (2 * BUF_BYTES)          /* 143360 */

#define TOT (4 * 16 * 2048 * 64)            /* 8388608 elements per tensor */

__device__ float g_Qc[TOT];
__device__ float g_Kc[TOT];
__device__ float g_Vc[TOT];

__device__ __forceinline__ unsigned tf32b(float x) {
    unsigned u;
    asm("cvt.rna.tf32.f32 %0, %1;" : "=r"(u) : "f"(x));
    return u;
}
__device__ __forceinline__ float ex2f(float x) {
    float r; asm("ex2.approx.f32 %0, %1;" : "=f"(r) : "f"(x)); return r;
}
__device__ __forceinline__ void mma_tf32(float c[4],
                                         const unsigned a[4],
                                         unsigned b0, unsigned b1) {
    asm("mma.sync.aligned.m16n8k8.row.col.f32.tf32.tf32.f32 "
        "{%0,%1,%2,%3}, {%4,%5,%6,%7}, {%8,%9}, {%0,%1,%2,%3};"
        : "+f"(c[0]), "+f"(c[1]), "+f"(c[2]), "+f"(c[3])
        : "r"(a[0]), "r"(a[1]), "r"(a[2]), "r"(a[3]), "r"(b0), "r"(b1));
}
__device__ __forceinline__ void cpa16(void* dst_smem, const void* src) {
    unsigned d = (unsigned)__cvta_generic_to_shared(dst_smem);
    asm volatile("cp.async.cg.shared.global [%0], [%1], 16;" :: "r"(d), "l"(src));
}
__device__ __forceinline__ void cpa_commit() {
    asm volatile("cp.async.commit_group;");
}
template <int N> __device__ __forceinline__ void cpa_wait() {
    asm volatile("cp.async.wait_group %0;" :: "n"(N));
}

// ---- prepass: fp32 -> tf32 bits (optionally scaled) ----
__global__ void __launch_bounds__(256) cvt_tf32_kernel(
    const float* __restrict__ src, float* __restrict__ dst, float scale)
{
    int idx = blockIdx.x * 256 + threadIdx.x;
    float4 v = ((const float4*)src)[idx];
    uint4 u;
    u.x = tf32b(v.x * scale);
    u.y = tf32b(v.y * scale);
    u.z = tf32b(v.z * scale);
    u.w = tf32b(v.w * scale);
    ((uint4*)dst)[idx] = u;
}

__global__ void __launch_bounds__(NT, 1) attn_tf32_pipe_kernel(
    float* __restrict__ O, int S)
{
    extern __shared__ char smem[];

    const int tid  = threadIdx.x;
    const int lane = tid & 31;
    const int warp = tid >> 5;
    const int gid  = lane >> 2;
    const int tig  = lane & 3;

    const size_t base = (size_t)blockIdx.y * ((size_t)S * DH);
    const int qbase = blockIdx.x * BM;

    const float* Kc = g_Kc + base;
    const float* Vc = g_Vc + base;

    unsigned* Ks[2] = { (unsigned*)smem, (unsigned*)(smem + BUF_BYTES) };
    unsigned* Vs[2] = { (unsigned*)(smem + KS_BYTES),
                        (unsigned*)(smem + BUF_BYTES + KS_BYTES) };

    // ---- prologue: async-stage Q (into buf1 Ks region) and tile 0 ----
    {
        const float* Qc = g_Qc + base + (size_t)qbase * DH;
        #pragma unroll
        for (int it = 0; it < 8; ++it) {
            int idx = tid + it * NT;
            int row = idx >> 4;
            int d4 = (idx & 15) << 2;
            cpa16(&Ks[1][row * KS_STRIDE + d4], &Qc[row * DH + d4]);
        }
        cpa_commit();
        #pragma unroll
        for (int it = 0; it < 8; ++it) {
            int idx = tid + it * NT;
            int row = idx >> 4;
            int d4 = (idx & 15) << 2;
            cpa16(&Ks[0][row * KS_STRIDE + d4], &Kc[row * DH + d4]);
            cpa16(&Vs[0][row * VS_STRIDE + d4], &Vc[row * DH + d4]);
        }
        cpa_commit();
    }

    cpa_wait<1>();          // Q ready
    __syncthreads();

    // ---- Q fragments resident: 8 d-chunks of m16k8 ----
    unsigned qa[8][4];
    {
        const int r0 = warp * 16 + gid;
        #pragma unroll
        for (int kc = 0; kc < 8; ++kc) {
            qa[kc][0] = Ks[1][(r0    ) * KS_STRIDE + kc * 8 + tig];
            qa[kc][1] = Ks[1][(r0 + 8) * KS_STRIDE + kc * 8 + tig];
            qa[kc][2] = Ks[1][(r0    ) * KS_STRIDE + kc * 8 + tig + 4];
            qa[kc][3] = Ks[1][(r0 + 8) * KS_STRIDE + kc * 8 + tig + 4];
        }
    }
    __syncthreads();        // all Q-frag reads done before buf1 is overwritten

    float o[8][4];
    #pragma unroll
    for (int nt = 0; nt < 8; ++nt)
        #pragma unroll
        for (int j = 0; j < 4; ++j) o[nt][j] = 0.0f;
    float m0 = -1e30f, m1 = -1e30f, l0 = 0.0f, l1 = 0.0f;

    const int srcA = (lane & 28) | (tig >> 1);
    const int srcB = srcA + 2;
    const bool odd = (tig & 1) != 0;

    const int nkt = S / BN;
    for (int kt = 0; kt < nkt; ++kt) {
        const int cur = kt & 1;

        // ---- prefetch tile kt+1 into the other buffer ----
        if (kt + 1 < nkt) {
            const int kb1 = (kt + 1) * BN;
            unsigned* Kn = Ks[cur ^ 1];
            unsigned* Vn = Vs[cur ^ 1];
            #pragma unroll
            for (int it = 0; it < 8; ++it) {
                int idx = tid + it * NT;
                int row = idx >> 4;
                int d4 = (idx & 15) << 2;
                cpa16(&Kn[row * KS_STRIDE + d4], &Kc[(size_t)(kb1 + row) * DH + d4]);
                cpa16(&Vn[row * VS_STRIDE + d4], &Vc[(size_t)(kb1 + row) * DH + d4]);
            }
            cpa_commit();
            cpa_wait<1>();   // tile kt complete
        } else {
            cpa_wait<0>();
        }
        __syncthreads();     // tile kt visible to all warps

        const unsigned* Kb = Ks[cur];
        const unsigned* Vb = Vs[cur];

        // ---- GEMM1: S = Q @ K^T (16 n-tiles of 16x8) ----
        float c[16][4];
        #pragma unroll
        for (int nt = 0; nt < 16; ++nt)
            #pragma unroll
            for (int j = 0; j < 4; ++j) c[nt][j] = 0.0f;

        #pragma unroll
        for (int kc = 0; kc < 8; ++kc) {
            #pragma unroll
            for (int nt = 0; nt < 16; ++nt) {
                unsigned b0 = Kb[(nt * 8 + gid) * KS_STRIDE + kc * 8 + tig];
                unsigned b1 = Kb[(nt * 8 + gid) * KS_STRIDE + kc * 8 + tig + 4];
                mma_tf32(c[nt], qa[kc], b0, b1);
            }
        }

        // ---- online softmax (log2 domain); rows gid, gid+8 ----
        float mx0 = -1e30f, mx1 = -1e30f;
        #pragma unroll
        for (int nt = 0; nt < 16; ++nt) {
            mx0 = fmaxf(mx0, fmaxf(c[nt][0], c[nt][1]));
            mx1 = fmaxf(mx1, fmaxf(c[nt][2], c[nt][3]));
        }
        #pragma unroll
        for (int off = 1; off <= 2; off <<= 1) {
            mx0 = fmaxf(mx0, __shfl_xor_sync(0xffffffffu, mx0, off));
            mx1 = fmaxf(mx1, __shfl_xor_sync(0xffffffffu, mx1, off));
        }
        float mn0 = fmaxf(m0, mx0), mn1 = fmaxf(m1, mx1);
        float f0 = ex2f(m0 - mn0), f1 = ex2f(m1 - mn1);
        m0 = mn0; m1 = mn1;

        float s0 = 0.0f, s1 = 0.0f;
        #pragma unroll
        for (int nt = 0; nt < 16; ++nt) {
            c[nt][0] = ex2f(c[nt][0] - mn0);
            c[nt][1] = ex2f(c[nt][1] - mn0);
            c[nt][2] = ex2f(c[nt][2] - mn1);
            c[nt][3] = ex2f(c[nt][3] - mn1);
            s0 += c[nt][0] + c[nt][1];
            s1 += c[nt][2] + c[nt][3];
        }
        #pragma unroll
        for (int off = 1; off <= 2; off <<= 1) {
            s0 += __shfl_xor_sync(0xffffffffu, s0, off);
            s1 += __shfl_xor_sync(0xffffffffu, s1, off);
        }
        l0 = l0 * f0 + s0;
        l1 = l1 * f1 + s1;

        #pragma unroll
        for (int nt = 0; nt < 8; ++nt) {
            o[nt][0] *= f0; o[nt][1] *= f0;
            o[nt][2] *= f1; o[nt][3] *= f1;
        }

        // ---- P: C-frag -> A-frag (quad shuffles), fused with GEMM2 ----
        #pragma unroll
        for (int kc = 0; kc < 16; ++kc) {
            float x0 = __shfl_sync(0xffffffffu, c[kc][0], srcA);
            float x1 = __shfl_sync(0xffffffffu, c[kc][1], srcA);
            float y0 = __shfl_sync(0xffffffffu, c[kc][0], srcB);
            float y1 = __shfl_sync(0xffffffffu, c[kc][1], srcB);
            float z0 = __shfl_sync(0xffffffffu, c[kc][2], srcA);
            float z1 = __shfl_sync(0xffffffffu, c[kc][3], srcA);
            float w0 = __shfl_sync(0xffffffffu, c[kc][2], srcB);
            float w1 = __shfl_sync(0xffffffffu, c[kc][3], srcB);
            unsigned pa[4];
            pa[0] = tf32b(odd ? x1 : x0);
            pa[2] = tf32b(odd ? y1 : y0);
            pa[1] = tf32b(odd ? z1 : z0);
            pa[3] = tf32b(odd ? w1 : w0);
            #pragma unroll
            for (int nt2 = 0; nt2 < 8; ++nt2) {
                unsigned b0 = Vb[(kc * 8 + tig    ) * VS_STRIDE + nt2 * 8 + gid];
                unsigned b1 = Vb[(kc * 8 + tig + 4) * VS_STRIDE + nt2 * 8 + gid];
                mma_tf32(o[nt2], pa, b0, b1);
            }
        }
        __syncthreads();     // compute done before next prefetch overwrites
    }

    // ---- epilogue ----
    const float inv0 = 1.0f / l0, inv1 = 1.0f / l1;
    const int r0 = qbase + warp * 16 + gid;
    const int r1 = r0 + 8;
    #pragma unroll
    for (int nt2 = 0; nt2 < 8; ++nt2) {
        float2 e0, e1;
        e0.x = o[nt2][0] * inv0; e0.y = o[nt2][1] * inv0;
        e1.x = o[nt2][2] * inv1; e1.y = o[nt2][3] * inv1;
        *(float2*)&O[base + (size_t)r0 * DH + nt2 * 8 + 2 * tig] = e0;
        *(float2*)&O[base + (size_t)r1 * DH + nt2 * 8 + 2 * tig] = e1;
    }
}

extern "C" void kernel_launch(void* const* d_in, const int* in_sizes, int n_in,
                              void* d_out, int out_size)
{
    const float* Q = (const float*)d_in[0];
    const float* K = (const float*)d_in[1];
    const float* V = (const float*)d_in[2];
    float* O = (float*)d_out;

    const int S = 2048;   // B=4, H=16, S=2048, D=64 fixed by the problem
    const float SC = 0.125f * 1.4426950408889634f;

    float *dQc, *dKc, *dVc;
    cudaGetSymbolAddress((void**)&dQc, g_Qc);
    cudaGetSymbolAddress((void**)&dKc, g_Kc);
    cudaGetSymbolAddress((void**)&dVc, g_Vc);

    const int n4 = TOT / 4;
    cvt_tf32_kernel<<<n4 / 256, 256>>>(Q, dQc, SC);
    cvt_tf32_kernel<<<n4 / 256, 256>>>(K, dKc, 1.0f);
    cvt_tf32_kernel<<<n4 / 256, 256>>>(V, dVc, 1.0f);

    cudaFuncSetAttribute(attn_tf32_pipe_kernel,
                         cudaFuncAttributeMaxDynamicSharedMemorySize, SMEM_BYTES);

    dim3 grid(S / BM, 64);
    attn_tf32_pipe_kernel<<<grid, NT, SMEM_BYTES>>>(O, S);
}

// round 12
// speedup vs baseline: 1.2996x; 1.2996x over previous
#include <cuda_runtime.h>

// Scaled dot-product attention, B=4 H=16 S=2048 D=64, fp32 in/out.
// R10: R6 tf32-MMA structure + cp.async double-buffered K/V pipeline,
// manually 2x-unrolled with compile-time buffer pointers (no spills).
// Prepass converts Q/K/V to tf32 bits (Q pre-scaled to log2 domain).

#define DH 64
#define BM 128
#define BN 128
#define NT 256
#define SEQ 2048
#define NKT (SEQ / BN)     /* 16 */

#define KS_STRIDE 68   /* words per K row: conflict-free B-fragment pattern */
#define VS_STRIDE 72   /* words per V row */
#define KS_BYTES (BN * KS_STRIDE * 4)       /* 34816 */
#define VS_BYTES (BN * VS_STRIDE * 4)       /* 36864 */
#define BUF_BYTES (KS_BYTES + VS_BYTES)     /* 71680 */
#define SMEM_BYTES (2 * BUF_BYTES)          /* 143360 */

#define TOT (4 * 16 * 2048 * 64)            /* 8388608 elements per tensor */

__device__ float g_Qc[TOT];
__device__ float g_Kc[TOT];
__device__ float g_Vc[TOT];

__device__ __forceinline__ unsigned tf32b(float x) {
    unsigned u;
    asm("cvt.rna.tf32.f32 %0, %1;" : "=r"(u) : "f"(x));
    return u;
}
__device__ __forceinline__ float ex2f(float x) {
    float r; asm("ex2.approx.f32 %0, %1;" : "=f"(r) : "f"(x)); return r;
}
__device__ __forceinline__ void mma_tf32(float c[4],
                                         const unsigned a[4],
                                         unsigned b0, unsigned b1) {
    asm("mma.sync.aligned.m16n8k8.row.col.f32.tf32.tf32.f32 "
        "{%0,%1,%2,%3}, {%4,%5,%6,%7}, {%8,%9}, {%0,%1,%2,%3};"
        : "+f"(c[0]), "+f"(c[1]), "+f"(c[2]), "+f"(c[3])
        : "r"(a[0]), "r"(a[1]), "r"(a[2]), "r"(a[3]), "r"(b0), "r"(b1));
}
__device__ __forceinline__ void cpa16(void* dst_smem, const void* src) {
    unsigned d = (unsigned)__cvta_generic_to_shared(dst_smem);
    asm volatile("cp.async.cg.shared.global [%0], [%1], 16;" :: "r"(d), "l"(src));
}
__device__ __forceinline__ void cpa_commit() {
    asm volatile("cp.async.commit_group;");
}
template <int N> __device__ __forceinline__ void cpa_wait() {
    asm volatile("cp.async.wait_group %0;" :: "n"(N));
}

// ---- prepass: fp32 -> tf32 bits (optionally scaled) ----
__global__ void __launch_bounds__(256) cvt_tf32_kernel(
    const float* __restrict__ src, float* __restrict__ dst, float scale)
{
    int idx = blockIdx.x * 256 + threadIdx.x;
    float4 v = ((const float4*)src)[idx];
    uint4 u;
    u.x = tf32b(v.x * scale);
    u.y = tf32b(v.y * scale);
    u.z = tf32b(v.z * scale);
    u.w = tf32b(v.w * scale);
    ((uint4*)dst)[idx] = u;
}

__device__ __forceinline__ void prefetch_tile(
    unsigned* __restrict__ Kn, unsigned* __restrict__ Vn,
    const float* __restrict__ Kc, const float* __restrict__ Vc,
    int kb, int tid)
{
    #pragma unroll
    for (int it = 0; it < 8; ++it) {
        int idx = tid + it * NT;
        int row = idx >> 4;
        int d4 = (idx & 15) << 2;
        cpa16(&Kn[row * KS_STRIDE + d4], &Kc[(size_t)(kb + row) * DH + d4]);
        cpa16(&Vn[row * VS_STRIDE + d4], &Vc[(size_t)(kb + row) * DH + d4]);
    }
    cpa_commit();
}

__device__ __forceinline__ void compute_tile(
    const unsigned* __restrict__ Kb, const unsigned* __restrict__ Vb,
    const unsigned (&qa)[8][4], float (&o)[8][4],
    float& m0, float& m1, float& l0, float& l1,
    int gid, int tig, int srcA, int srcB, bool odd)
{
    // ---- GEMM1: S = Q @ K^T (16 n-tiles of 16x8) ----
    float c[16][4];
    #pragma unroll
    for (int nt = 0; nt < 16; ++nt)
        #pragma unroll
        for (int j = 0; j < 4; ++j) c[nt][j] = 0.0f;

    #pragma unroll
    for (int kc = 0; kc < 8; ++kc) {
        #pragma unroll
        for (int nt = 0; nt < 16; ++nt) {
            unsigned b0 = Kb[(nt * 8 + gid) * KS_STRIDE + kc * 8 + tig];
            unsigned b1 = Kb[(nt * 8 + gid) * KS_STRIDE + kc * 8 + tig + 4];
            mma_tf32(c[nt], qa[kc], b0, b1);
        }
    }

    // ---- online softmax (log2 domain); rows gid, gid+8 ----
    float mx0 = -1e30f, mx1 = -1e30f;
    #pragma unroll
    for (int nt = 0; nt < 16; ++nt) {
        mx0 = fmaxf(mx0, fmaxf(c[nt][0], c[nt][1]));
        mx1 = fmaxf(mx1, fmaxf(c[nt][2], c[nt][3]));
    }
    #pragma unroll
    for (int off = 1; off <= 2; off <<= 1) {
        mx0 = fmaxf(mx0, __shfl_xor_sync(0xffffffffu, mx0, off));
        mx1 = fmaxf(mx1, __shfl_xor_sync(0xffffffffu, mx1, off));
    }
    float mn0 = fmaxf(m0, mx0), mn1 = fmaxf(m1, mx1);
    float f0 = ex2f(m0 - mn0), f1 = ex2f(m1 - mn1);
    m0 = mn0; m1 = mn1;

    float s0 = 0.0f, s1 = 0.0f;
    #pragma unroll
    for (int nt = 0; nt < 16; ++nt) {
        c[nt][0] = ex2f(c[nt][0] - mn0);
        c[nt][1] = ex2f(c[nt][1] - mn0);
        c[nt][2] = ex2f(c[nt][2] - mn1);
        c[nt][3] = ex2f(c[nt][3] - mn1);
        s0 += c[nt][0] + c[nt][1];
        s1 += c[nt][2] + c[nt][3];
    }
    #pragma unroll
    for (int off = 1; off <= 2; off <<= 1) {
        s0 += __shfl_xor_sync(0xffffffffu, s0, off);
        s1 += __shfl_xor_sync(0xffffffffu, s1, off);
    }
    l0 = l0 * f0 + s0;
    l1 = l1 * f1 + s1;

    #pragma unroll
    for (int nt = 0; nt < 8; ++nt) {
        o[nt][0] *= f0; o[nt][1] *= f0;
        o[nt][2] *= f1; o[nt][3] *= f1;
    }

    // ---- P: C-frag -> A-frag (quad shuffles), fused with GEMM2 ----
    #pragma unroll
    for (int kc = 0; kc < 16; ++kc) {
        float x0 = __shfl_sync(0xffffffffu, c[kc][0], srcA);
        float x1 = __shfl_sync(0xffffffffu, c[kc][1], srcA);
        float y0 = __shfl_sync(0xffffffffu, c[kc][0], srcB);
        float y1 = __shfl_sync(0xffffffffu, c[kc][1], srcB);
        float z0 = __shfl_sync(0xffffffffu, c[kc][2], srcA);
        float z1 = __shfl_sync(0xffffffffu, c[kc][3], srcA);
        float w0 = __shfl_sync(0xffffffffu, c[kc][2], srcB);
        float w1 = __shfl_sync(0xffffffffu, c[kc][3], srcB);
        unsigned pa[4];
        pa[0] = tf32b(odd ? x1 : x0);
        pa[2] = tf32b(odd ? y1 : y0);
        pa[1] = tf32b(odd ? z1 : z0);
        pa[3] = tf32b(odd ? w1 : w0);
        #pragma unroll
        for (int nt2 = 0; nt2 < 8; ++nt2) {
            unsigned b0 = Vb[(kc * 8 + tig    ) * VS_STRIDE + nt2 * 8 + gid];
            unsigned b1 = Vb[(kc * 8 + tig + 4) * VS_STRIDE + nt2 * 8 + gid];
            mma_tf32(o[nt2], pa, b0, b1);
        }
    }
}

__global__ void __launch_bounds__(NT, 1) attn_tf32_pipe2_kernel(float* __restrict__ O)
{
    extern __shared__ char smem[];
    unsigned* Ks0 = (unsigned*)smem;
    unsigned* Vs0 = (unsigned*)(smem + KS_BYTES);
    unsigned* Ks1 = (unsigned*)(smem + BUF_BYTES);
    unsigned* Vs1 = (unsigned*)(smem + BUF_BYTES + KS_BYTES);

    const int tid  = threadIdx.x;
    const int lane = tid & 31;
    const int warp = tid >> 5;
    const int gid  = lane >> 2;
    const int tig  = lane & 3;

    const size_t base = (size_t)blockIdx.y * ((size_t)SEQ * DH);
    const int qbase = blockIdx.x * BM;

    const float* Kc = g_Kc + base;
    const float* Vc = g_Vc + base;

    // ---- prologue: async-stage Q (into Ks1 region) then tile 0 into buf0 ----
    {
        const float* Qc = g_Qc + base + (size_t)qbase * DH;
        #pragma unroll
        for (int it = 0; it < 8; ++it) {
            int idx = tid + it * NT;
            int row = idx >> 4;
            int d4 = (idx & 15) << 2;
            cpa16(&Ks1[row * KS_STRIDE + d4], &Qc[row * DH + d4]);
        }
        cpa_commit();
    }
    prefetch_tile(Ks0, Vs0, Kc, Vc, 0, tid);

    cpa_wait<1>();          // Q ready (tile 0 may still fly)
    __syncthreads();

    unsigned qa[8][4];
    {
        const int r0 = warp * 16 + gid;
        #pragma unroll
        for (int kc = 0; kc < 8; ++kc) {
            qa[kc][0] = Ks1[(r0    ) * KS_STRIDE + kc * 8 + tig];
            qa[kc][1] = Ks1[(r0 + 8) * KS_STRIDE + kc * 8 + tig];
            qa[kc][2] = Ks1[(r0    ) * KS_STRIDE + kc * 8 + tig + 4];
            qa[kc][3] = Ks1[(r0 + 8) * KS_STRIDE + kc * 8 + tig + 4];
        }
    }
    __syncthreads();        // Q-frag reads done before Ks1 is reused

    float o[8][4];
    #pragma unroll
    for (int nt = 0; nt < 8; ++nt)
        #pragma unroll
        for (int j = 0; j < 4; ++j) o[nt][j] = 0.0f;
    float m0 = -1e30f, m1 = -1e30f, l0 = 0.0f, l1 = 0.0f;

    const int srcA = (lane & 28) | (tig >> 1);
    const int srcB = srcA + 2;
    const bool odd = (tig & 1) != 0;

    #pragma unroll 1
    for (int kt2 = 0; kt2 < NKT / 2; ++kt2) {
        const int ktB = 2 * kt2 + 1;

        // ---- step A: prefetch tile ktB into buf1; compute buf0 ----
        prefetch_tile(Ks1, Vs1, Kc, Vc, ktB * BN, tid);
        cpa_wait<1>();       // tile 2*kt2 complete
        __syncthreads();
        compute_tile(Ks0, Vs0, qa, o, m0, m1, l0, l1,
                     gid, tig, srcA, srcB, odd);
        __syncthreads();     // buf0 consumers done before next prefetch into it

        // ---- step B: prefetch tile ktB+1 into buf0; compute buf1 ----
        if (kt2 < NKT / 2 - 1) {
            prefetch_tile(Ks0, Vs0, Kc, Vc, (ktB + 1) * BN, tid);
            cpa_wait<1>();   // tile ktB complete
        } else {
            cpa_wait<0>();   // last tile: drain everything
        }
        __syncthreads();
        compute_tile(Ks1, Vs1, qa, o, m0, m1, l0, l1,
                     gid, tig, srcA, srcB, odd);
        __syncthreads();     // buf1 consumers done before next prefetch into it
    }

    // ---- epilogue ----
    const float inv0 = 1.0f / l0, inv1 = 1.0f / l1;
    const int r0 = qbase + warp * 16 + gid;
    const int r1 = r0 + 8;
    #pragma unroll
    for (int nt2 = 0; nt2 < 8; ++nt2) {
        float2 e0, e1;
        e0.x = o[nt2][0] * inv0; e0.y = o[nt2][1] * inv0;
        e1.x = o[nt2][2] * inv1; e1.y = o[nt2][3] * inv1;
        *(float2*)&O[base + (size_t)r0 * DH + nt2 * 8 + 2 * tig] = e0;
        *(float2*)&O[base + (size_t)r1 * DH + nt2 * 8 + 2 * tig] = e1;
    }
}

extern "C" void kernel_launch(void* const* d_in, const int* in_sizes, int n_in,
                              void* d_out, int out_size)
{
    const float* Q = (const float*)d_in[0];
    const float* K = (const float*)d_in[1];
    const float* V = (const float*)d_in[2];
    float* O = (float*)d_out;

    const float SC = 0.125f * 1.4426950408889634f;

    float *dQc, *dKc, *dVc;
    cudaGetSymbolAddress((void**)&dQc, g_Qc);
    cudaGetSymbolAddress((void**)&dKc, g_Kc);
    cudaGetSymbolAddress((void**)&dVc, g_Vc);

    const int n4 = TOT / 4;
    cvt_tf32_kernel<<<n4 / 256, 256>>>(Q, dQc, SC);
    cvt_tf32_kernel<<<n4 / 256, 256>>>(K, dKc, 1.0f);
    cvt_tf32_kernel<<<n4 / 256, 256>>>(V, dVc, 1.0f);

    cudaFuncSetAttribute(attn_tf32_pipe2_kernel,
                         cudaFuncAttributeMaxDynamicSharedMemorySize, SMEM_BYTES);

    dim3 grid(SEQ / BM, 64);
    attn_tf32_pipe2_kernel<<<grid, NT, SMEM_BYTES>>>(O);
}

// round 13
// speedup vs baseline: 1.4461x; 1.1127x over previous
#include <cuda_runtime.h>

// Scaled dot-product attention, B=4 H=16 S=2048 D=64, fp32 in/out.
// R12: R10 pipeline + permuted layouts so all MMA B/A fragments load as LDS.64.
//  - Q/K prepass permutes each 8-word d-group: slot = (t&3)*2 + (t>>2),
//    making fragment pairs (t, t+4) adjacent.
//  - V prepass transposes per head to Vt[d][k] with the same within-8 k-perm.
// Main loop: cp.async double-buffered, 2x-unrolled, compile-time buffers.

#define DH 64
#define BM 128
#define BN 128
#define NT 256
#define SEQ 2048
#define NKT (SEQ / BN)     /* 16 */

#define KS_STRIDE 72       /* words per K row; 72 % 32 == 8 -> conflict-free LDS.64 */
#define VT_STRIDE 136      /* words per Vt row; 136 % 32 == 8 */
#define KS_BYTES (BN * KS_STRIDE * 4)       /* 36864 */
#define VT_BYTES (DH * VT_STRIDE * 4)       /* 34816 */
#define BUF_BYTES (KS_BYTES + VT_BYTES)     /* 71680 */
#define SMEM_BYTES (2 * BUF_BYTES)          /* 143360 */

#define TOT (4 * 16 * 2048 * 64)            /* 8388608 elements per tensor */

__device__ float g_Qc[TOT];   // permuted-d, scaled, tf32 bits
__device__ float g_Kc[TOT];   // permuted-d, tf32 bits
__device__ float g_Vt[TOT];   // per-head transposed [d][k], permuted-k, tf32 bits

__device__ __forceinline__ unsigned tf32b(float x) {
    unsigned u;
    asm("cvt.rna.tf32.f32 %0, %1;" : "=r"(u) : "f"(x));
    return u;
}
__device__ __forceinline__ float ex2f(float x) {
    float r; asm("ex2.approx.f32 %0, %1;" : "=f"(r) : "f"(x)); return r;
}
__device__ __forceinline__ void mma_tf32(float c[4],
                                         const unsigned a[4],
                                         unsigned b0, unsigned b1) {
    asm("mma.sync.aligned.m16n8k8.row.col.f32.tf32.tf32.f32 "
        "{%0,%1,%2,%3}, {%4,%5,%6,%7}, {%8,%9}, {%0,%1,%2,%3};"
        : "+f"(c[0]), "+f"(c[1]), "+f"(c[2]), "+f"(c[3])
        : "r"(a[0]), "r"(a[1]), "r"(a[2]), "r"(a[3]), "r"(b0), "r"(b1));
}
__device__ __forceinline__ void cpa16(void* dst_smem, const void* src) {
    unsigned d = (unsigned)__cvta_generic_to_shared(dst_smem);
    asm volatile("cp.async.cg.shared.global [%0], [%1], 16;" :: "r"(d), "l"(src));
}
__device__ __forceinline__ void cpa_commit() {
    asm volatile("cp.async.commit_group;");
}
template <int N> __device__ __forceinline__ void cpa_wait() {
    asm volatile("cp.async.wait_group %0;" :: "n"(N));
}

// ---- prepass A: fp32 -> tf32 bits, permute each 8-word d-group ----
// out slots {0..7} = in t {0,4,1,5,2,6,3,7}
__global__ void __launch_bounds__(256) cvt_perm_kernel(
    const float* __restrict__ src, float* __restrict__ dst, float scale)
{
    int i = blockIdx.x * 256 + threadIdx.x;      // one 8-word group per thread
    const float4* s = (const float4*)(src) + 2 * i;
    float4 in0 = s[0];          // t = 0..3
    float4 in1 = s[1];          // t = 4..7
    uint4 o0, o1;
    o0.x = tf32b(in0.x * scale);  o0.y = tf32b(in1.x * scale);
    o0.z = tf32b(in0.y * scale);  o0.w = tf32b(in1.y * scale);
    o1.x = tf32b(in0.z * scale);  o1.y = tf32b(in1.z * scale);
    o1.z = tf32b(in0.w * scale);  o1.w = tf32b(in1.w * scale);
    uint4* d = (uint4*)(dst) + 2 * i;
    d[0] = o0;
    d[1] = o1;
}

// ---- prepass B: per-head transpose V[k][d] -> Vt[d][k'], k' perm within 8 ----
__global__ void __launch_bounds__(256) transpose_v_kernel(
    const float* __restrict__ V, float* __restrict__ Vt)
{
    __shared__ float t[32][33];
    const int k0 = blockIdx.x * 32;
    const int d0 = blockIdx.y * 32;
    const size_t hb = (size_t)blockIdx.z * (SEQ * DH);
    const int txi = threadIdx.x;   // 0..31
    const int tyi = threadIdx.y;   // 0..7

    #pragma unroll
    for (int j = 0; j < 4; ++j) {
        int k = k0 + tyi + j * 8;
        t[tyi + j * 8][txi] = V[hb + (size_t)k * DH + d0 + txi];
    }
    __syncthreads();
    const int kp = k0 + ((txi & ~7) | ((txi & 3) << 1) | ((txi & 7) >> 2));
    #pragma unroll
    for (int j = 0; j < 4; ++j) {
        int d = d0 + tyi + j * 8;
        unsigned u = tf32b(t[txi][tyi + j * 8]);
        Vt[hb + (size_t)d * SEQ + kp] = __uint_as_float(u);
    }
}

__device__ __forceinline__ void prefetch_tile(
    unsigned* __restrict__ Kn, unsigned* __restrict__ Vn,
    const float* __restrict__ Kc, const float* __restrict__ Vtc,
    int kb, int tid)
{
    #pragma unroll
    for (int it = 0; it < 8; ++it) {             // K: 128 rows x 64 words
        int idx = tid + it * NT;
        int row = idx >> 4;
        int d4 = (idx & 15) << 2;
        cpa16(&Kn[row * KS_STRIDE + d4], &Kc[(size_t)(kb + row) * DH + d4]);
    }
    #pragma unroll
    for (int it = 0; it < 8; ++it) {             // Vt: 64 rows x 128 words
        int idx = tid + it * NT;
        int row = idx >> 5;
        int c4 = (idx & 31) << 2;
        cpa16(&Vn[row * VT_STRIDE + c4], &Vtc[(size_t)row * SEQ + kb + c4]);
    }
    cpa_commit();
}

__device__ __forceinline__ void compute_tile(
    const unsigned* __restrict__ Kb, const unsigned* __restrict__ Vb,
    const unsigned (&qa)[8][4], float (&o)[8][4],
    float& m0, float& m1, float& l0, float& l1,
    int gid, int tig, int srcA, int srcB, bool odd)
{
    // ---- GEMM1: S = Q @ K^T (16 n-tiles of 16x8); B-frags are LDS.64 ----
    float c[16][4];
    #pragma unroll
    for (int nt = 0; nt < 16; ++nt)
        #pragma unroll
        for (int j = 0; j < 4; ++j) c[nt][j] = 0.0f;

    #pragma unroll
    for (int kc = 0; kc < 8; ++kc) {
        #pragma unroll
        for (int nt = 0; nt < 16; ++nt) {
            uint2 b = *(const uint2*)&Kb[(nt * 8 + gid) * KS_STRIDE + kc * 8 + 2 * tig];
            mma_tf32(c[nt], qa[kc], b.x, b.y);
        }
    }

    // ---- online softmax (log2 domain); rows gid, gid+8 ----
    float mx0 = -1e30f, mx1 = -1e30f;
    #pragma unroll
    for (int nt = 0; nt < 16; ++nt) {
        mx0 = fmaxf(mx0, fmaxf(c[nt][0], c[nt][1]));
        mx1 = fmaxf(mx1, fmaxf(c[nt][2], c[nt][3]));
    }
    #pragma unroll
    for (int off = 1; off <= 2; off <<= 1) {
        mx0 = fmaxf(mx0, __shfl_xor_sync(0xffffffffu, mx0, off));
        mx1 = fmaxf(mx1, __shfl_xor_sync(0xffffffffu, mx1, off));
    }
    float mn0 = fmaxf(m0, mx0), mn1 = fmaxf(m1, mx1);
    float f0 = ex2f(m0 - mn0), f1 = ex2f(m1 - mn1);
    m0 = mn0; m1 = mn1;

    float s0 = 0.0f, s1 = 0.0f;
    #pragma unroll
    for (int nt = 0; nt < 16; ++nt) {
        c[nt][0] = ex2f(c[nt][0] - mn0);
        c[nt][1] = ex2f(c[nt][1] - mn0);
        c[nt][2] = ex2f(c[nt][2] - mn1);
        c[nt][3] = ex2f(c[nt][3] - mn1);
        s0 += c[nt][0] + c[nt][1];
        s1 += c[nt][2] + c[nt][3];
    }
    #pragma unroll
    for (int off = 1; off <= 2; off <<= 1) {
        s0 += __shfl_xor_sync(0xffffffffu, s0, off);
        s1 += __shfl_xor_sync(0xffffffffu, s1, off);
    }
    l0 = l0 * f0 + s0;
    l1 = l1 * f1 + s1;

    #pragma unroll
    for (int nt = 0; nt < 8; ++nt) {
        o[nt][0] *= f0; o[nt][1] *= f0;
        o[nt][2] *= f1; o[nt][3] *= f1;
    }

    // ---- P: C-frag -> A-frag (quad shuffles), fused with GEMM2 ----
    #pragma unroll
    for (int kc = 0; kc < 16; ++kc) {
        float x0 = __shfl_sync(0xffffffffu, c[kc][0], srcA);
        float x1 = __shfl_sync(0xffffffffu, c[kc][1], srcA);
        float y0 = __shfl_sync(0xffffffffu, c[kc][0], srcB);
        float y1 = __shfl_sync(0xffffffffu, c[kc][1], srcB);
        float z0 = __shfl_sync(0xffffffffu, c[kc][2], srcA);
        float z1 = __shfl_sync(0xffffffffu, c[kc][3], srcA);
        float w0 = __shfl_sync(0xffffffffu, c[kc][2], srcB);
        float w1 = __shfl_sync(0xffffffffu, c[kc][3], srcB);
        unsigned pa[4];
        pa[0] = tf32b(odd ? x1 : x0);
        pa[2] = tf32b(odd ? y1 : y0);
        pa[1] = tf32b(odd ? z1 : z0);
        pa[3] = tf32b(odd ? w1 : w0);
        #pragma unroll
        for (int nt2 = 0; nt2 < 8; ++nt2) {
            uint2 b = *(const uint2*)&Vb[(nt2 * 8 + gid) * VT_STRIDE + kc * 8 + 2 * tig];
            mma_tf32(o[nt2], pa, b.x, b.y);
        }
    }
}

__global__ void __launch_bounds__(NT, 1) attn_tf32_v2_kernel(float* __restrict__ O)
{
    extern __shared__ char smem[];
    unsigned* Ks0 = (unsigned*)smem;
    unsigned* Vs0 = (unsigned*)(smem + KS_BYTES);
    unsigned* Ks1 = (unsigned*)(smem + BUF_BYTES);
    unsigned* Vs1 = (unsigned*)(smem + BUF_BYTES + KS_BYTES);

    const int tid  = threadIdx.x;
    const int lane = tid & 31;
    const int warp = tid >> 5;
    const int gid  = lane >> 2;
    const int tig  = lane & 3;

    const size_t base = (size_t)blockIdx.y * ((size_t)SEQ * DH);
    const int qbase = blockIdx.x * BM;

    const float* Kc  = g_Kc + base;
    const float* Vtc = g_Vt + base;

    // ---- prologue: async-stage Q (into Ks1 region) then tile 0 into buf0 ----
    {
        const float* Qc = g_Qc + base + (size_t)qbase * DH;
        #pragma unroll
        for (int it = 0; it < 8; ++it) {
            int idx = tid + it * NT;
            int row = idx >> 4;
            int d4 = (idx & 15) << 2;
            cpa16(&Ks1[row * KS_STRIDE + d4], &Qc[row * DH + d4]);
        }
        cpa_commit();
    }
    prefetch_tile(Ks0, Vs0, Kc, Vtc, 0, tid);

    cpa_wait<1>();          // Q ready (tile 0 may still fly)
    __syncthreads();

    unsigned qa[8][4];      // permuted layout: (a0,a2) and (a1,a3) adjacent
    {
        const int r0 = warp * 16 + gid;
        #pragma unroll
        for (int kc = 0; kc < 8; ++kc) {
            uint2 lo = *(const uint2*)&Ks1[(r0    ) * KS_STRIDE + kc * 8 + 2 * tig];
            uint2 hi = *(const uint2*)&Ks1[(r0 + 8) * KS_STRIDE + kc * 8 + 2 * tig];
            qa[kc][0] = lo.x;  qa[kc][2] = lo.y;
            qa[kc][1] = hi.x;  qa[kc][3] = hi.y;
        }
    }
    __syncthreads();        // Q-frag reads done before Ks1 is reused

    float o[8][4];
    #pragma unroll
    for (int nt = 0; nt < 8; ++nt)
        #pragma unroll
        for (int j = 0; j < 4; ++j) o[nt][j] = 0.0f;
    float m0 = -1e30f, m1 = -1e30f, l0 = 0.0f, l1 = 0.0f;

    const int srcA = (lane & 28) | (tig >> 1);
    const int srcB = srcA + 2;
    const bool odd = (tig & 1) != 0;

    #pragma unroll 1
    for (int kt2 = 0; kt2 < NKT / 2; ++kt2) {
        const int ktB = 2 * kt2 + 1;

        // ---- step A: prefetch tile ktB into buf1; compute buf0 ----
        prefetch_tile(Ks1, Vs1, Kc, Vtc, ktB * BN, tid);
        cpa_wait<1>();       // tile 2*kt2 complete
        __syncthreads();
        compute_tile(Ks0, Vs0, qa, o, m0, m1, l0, l1,
                     gid, tig, srcA, srcB, odd);
        __syncthreads();     // buf0 consumers done before next prefetch into it

        // ---- step B: prefetch tile ktB+1 into buf0; compute buf1 ----
        if (kt2 < NKT / 2 - 1) {
            prefetch_tile(Ks0, Vs0, Kc, Vtc, (ktB + 1) * BN, tid);
            cpa_wait<1>();   // tile ktB complete
        } else {
            cpa_wait<0>();   // last tile: drain everything
        }
        __syncthreads();
        compute_tile(Ks1, Vs1, qa, o, m0, m1, l0, l1,
                     gid, tig, srcA, srcB, odd);
        __syncthreads();     // buf1 consumers done before next prefetch into it
    }

    // ---- epilogue ----
    const float inv0 = 1.0f / l0, inv1 = 1.0f / l1;
    const int r0 = qbase + warp * 16 + gid;
    const int r1 = r0 + 8;
    #pragma unroll
    for (int nt2 = 0; nt2 < 8; ++nt2) {
        float2 e0, e1;
        e0.x = o[nt2][0] * inv0; e0.y = o[nt2][1] * inv0;
        e1.x = o[nt2][2] * inv1; e1.y = o[nt2][3] * inv1;
        *(float2*)&O[base + (size_t)r0 * DH + nt2 * 8 + 2 * tig] = e0;
        *(float2*)&O[base + (size_t)r1 * DH + nt2 * 8 + 2 * tig] = e1;
    }
}

extern "C" void kernel_launch(void* const* d_in, const int* in_sizes, int n_in,
                              void* d_out, int out_size)
{
    const float* Q = (const float*)d_in[0];
    const float* K = (const float*)d_in[1];
    const float* V = (const float*)d_in[2];
    float* O = (float*)d_out;

    const float SC = 0.125f * 1.4426950408889634f;

    float *dQc, *dKc, *dVt;
    cudaGetSymbolAddress((void**)&dQc, g_Qc);
    cudaGetSymbolAddress((void**)&dKc, g_Kc);
    cudaGetSymbolAddress((void**)&dVt, g_Vt);

    const int n8 = TOT / 8;
    cvt_perm_kernel<<<n8 / 256, 256>>>(Q, dQc, SC);
    cvt_perm_kernel<<<n8 / 256, 256>>>(K, dKc, 1.0f);

    dim3 tg(SEQ / 32, DH / 32, 64);
    transpose_v_kernel<<<tg, dim3(32, 8)>>>(V, dVt);

    cudaFuncSetAttribute(attn_tf32_v2_kernel,
                         cudaFuncAttributeMaxDynamicSharedMemorySize, SMEM_BYTES);

    dim3 grid(SEQ / BM, 64);
    attn_tf32_v2_kernel<<<grid, NT, SMEM_BYTES>>>(O);
}